// round 6
// baseline (speedup 1.0000x reference)
#include <cuda_runtime.h>

// Izhikevich 6-neuron network, T sequential steps.
// warp0 (tid 0):  LLBN->EBN->IFN recurrence. Spikes as int bit-masks (alu pipe),
//                 v/u/core exactly as R2 (fma pipe). ~25 fma + ~18 alu per step.
// warp1 (tid 32): TN->MN, same mask scheme, int4 mask feed.
// warp2 (tid 64): 32-lane store warp; converts masks -> 0.0/1.0 floats.
// Output: [spikes[5][T] | volts[5][T]]

#define BATCH 32
#define RS_MASK 255
#define RING_BATCHES 8

__device__ __forceinline__ void st_rel(int* p, int v) {
    asm volatile("st.release.cta.u32 [%0], %1;" :: "l"(p), "r"(v) : "memory");
}
__device__ __forceinline__ int ld_acq(int* p) {
    int v;
    asm volatile("ld.acquire.cta.u32 %0, [%1];" : "=r"(v) : "l"(p) : "memory");
    return v;
}
__device__ __forceinline__ int fbits(float x) { return __float_as_int(x); }
__device__ __forceinline__ float ibits(int x) { return __int_as_float(x); }

__global__ void __launch_bounds__(128, 1)
izh_net7(const float* __restrict__ in_mat, int n_mat,
         const float* __restrict__ w12, float* __restrict__ out, int T) {
    // ring0: [m2, m3, m4, pad, v2, v3, v4, pad]  (m* are int masks: ~0 = NO spike)
    __shared__ __align__(16) float ring0[256 * 8];
    // ring1: [m5, v5, m6, v6]
    __shared__ __align__(16) float ring1[256 * 4];
    __shared__ __align__(16) int   ringz[256];      // m3 stream for warp1
    __shared__ float red[4];
    __shared__ int fl[3];

    const int tid = threadIdx.x;
    if (tid == 0) { fl[0] = 0; fl[1] = 0; fl[2] = 0; }

    // ---- reduction: sum(input_mat) ----
    float s = 0.0f;
    for (int i = tid; i < n_mat; i += 128) s += in_mat[i];
    #pragma unroll
    for (int o = 16; o; o >>= 1) s += __shfl_xor_sync(0xffffffffu, s, o);
    if ((tid & 31) == 0) red[tid >> 5] = s;
    __syncthreads();

    const int nbat = (T + BATCH - 1) / BATCH;

    // ================= warp0 lane0: LLBN -> EBN -> IFN =================
    if (tid == 0) {
        const float total = red[0] + red[1] + red[2] + red[3];
        const float z_plus = total * w12[0];
        const float C2 = 35.0f + 0.25f * w12[2] * (z_plus * w12[1]);
        const float C3 = 35.0f + 0.25f * (z_plus * w12[4]);
        const int A2b = fbits(-0.25f * w12[2] * w12[7]);  // coupling z4(t-1)
        const int B2b = fbits(0.25f * w12[3]);            // coupling z2(t-1)
        const int A3b = fbits(0.25f * w12[5]);            // coupling z2(t)
        const int A4b = fbits(0.25f * w12[6]);            // coupling z3(t)
        const int c2b = fbits(-55.0f), c3b = fbits(-55.0f), c4b = fbits(-65.0f);
        const int d2b = fbits(6.0f), d3b = fbits(0.05f), d4b = fbits(6.0f);

        float v2 = -60.0f, u2 = 4.5f;
        float v3 = -64.0f, u3 = -16.0f;
        float v4 = -64.0f, u4 = -16.0f;
        int m2p = ~0, m4p = ~0;   // no spike initially
        float core2 = fmaf(v2, fmaf(v2, 0.01f, 2.25f), fmaf(u2, -0.25f, C2));
        float core3 = fmaf(v3, fmaf(v3, 0.01f, 2.25f), fmaf(u3, -0.25f, C3));
        float core4 = fmaf(v4, fmaf(v4, 0.01f, 2.25f), fmaf(u4, -0.25f, 35.0f));

        int si = 0;
        for (int b = 0; b < nbat; ++b) {
            while (b - ld_acq(&fl[2]) >= RING_BATCHES) { }
            const int n = min(BATCH, T - b * BATCH);
            #pragma unroll 4
            for (int i = 0; i < n; ++i, ++si) {
                // ---- LLBN (a=.1,b=-.075,c=-55,d=6) ----
                float x2  = core2 + ibits(~m2p & B2b);
                float v12 = x2 + ibits(~m4p & A2b);
                int   m2  = fbits(v12 - 30.0f) >> 31;      // ~0 = no spike
                float nv2 = ibits((m2 & fbits(v12)) | (~m2 & c2b));
                float nu2 = fmaf(u2, 0.975f, v2 * -0.001875f);
                u2 = nu2 + ibits(~m2 & d2b);
                core2 = fmaf(nv2, fmaf(nv2, 0.01f, 2.25f), fmaf(u2, -0.25f, C2));
                v2 = nv2;
                // ---- EBN (a=.02,b=.25,c=-55,d=.05) ----
                float v13 = core3 + ibits(~m2 & A3b);
                int   m3  = fbits(v13 - 30.0f) >> 31;
                float nv3 = ibits((m3 & fbits(v13)) | (~m3 & c3b));
                float nu3 = fmaf(u3, 0.995f, v3 * 0.00125f);
                u3 = nu3 + ibits(~m3 & d3b);
                core3 = fmaf(nv3, fmaf(nv3, 0.01f, 2.25f), fmaf(u3, -0.25f, C3));
                v3 = nv3;
                // ---- IFN (a=.02,b=.25,c=-65,d=6) ----
                float v14 = core4 + ibits(~m3 & A4b);
                int   m4  = fbits(v14 - 30.0f) >> 31;
                float nv4 = ibits((m4 & fbits(v14)) | (~m4 & c4b));
                float nu4 = fmaf(u4, 0.995f, v4 * 0.00125f);
                u4 = nu4 + ibits(~m4 & d4b);
                core4 = fmaf(nv4, fmaf(nv4, 0.01f, 2.25f), fmaf(u4, -0.25f, 35.0f));
                v4 = nv4;

                m2p = m2; m4p = m4;
                // ---- publish (ints for masks, floats for volts) ----
                const int idx = (si & RS_MASK) * 8;
                ((int*)ring0)[idx + 0] = m2;
                ((int*)ring0)[idx + 1] = m3;
                ((int*)ring0)[idx + 2] = m4;
                ring0[idx + 4] = v2;
                ring0[idx + 5] = v3;
                ring0[idx + 6] = v4;
                ringz[si & RS_MASK] = m3;
            }
            st_rel(&fl[0], b + 1);
        }
        return;
    }

    // ================= warp1 lane0: TN -> MN =================
    if (tid == 32) {
        const int A5b = fbits(0.25f * w12[9] * w12[8]);   // * z3(t)
        const int B5b = fbits(0.25f * w12[10]);           // * z5(t-1)
        const int A6b = fbits(0.25f * w12[11]);           // * z5(t)
        const int c5b = fbits(-65.0f), c6b = fbits(-65.0f);
        const int d5b = fbits(6.0f),  d6b = fbits(6.0f);

        float v5 = -70.0f, u5 = -14.0f;
        float v6 = -64.0f, u6 = -16.0f;
        int m5p = ~0;
        float core5 = fmaf(v5, fmaf(v5, 0.01f, 2.25f), fmaf(u5, -0.25f, 35.0f));
        float core6 = fmaf(v6, fmaf(v6, 0.01f, 2.25f), fmaf(u6, -0.25f, 35.0f));

        int si = 0;
        for (int b = 0; b < nbat; ++b) {
            while (ld_acq(&fl[0]) <= b) { }
            const int n = min(BATCH, T - b * BATCH);
            for (int i4 = 0; i4 < n; i4 += 4) {
                int4 mq = *reinterpret_cast<int4*>(&ringz[si & RS_MASK]);
                int m3v[4] = {mq.x, mq.y, mq.z, mq.w};
                const int jmax = min(4, n - i4);
                #pragma unroll 4
                for (int j = 0; j < jmax; ++j, ++si) {
                    int m3 = m3v[j];
                    // ---- TN (a=.02,b=.2,c=-65,d=6) ----
                    float x5  = core5 + ibits(~m3 & A5b);
                    float v15 = x5 + ibits(~m5p & B5b);
                    int   m5  = fbits(v15 - 30.0f) >> 31;
                    float nv5 = ibits((m5 & fbits(v15)) | (~m5 & c5b));
                    float nu5 = fmaf(u5, 0.995f, v5 * 0.001f);
                    u5 = nu5 + ibits(~m5 & d5b);
                    core5 = fmaf(nv5, fmaf(nv5, 0.01f, 2.25f), fmaf(u5, -0.25f, 35.0f));
                    v5 = nv5;
                    // ---- MN (a=.02,b=.25,c=-65,d=6) ----
                    float v16 = core6 + ibits(~m5 & A6b);
                    int   m6  = fbits(v16 - 30.0f) >> 31;
                    float nv6 = ibits((m6 & fbits(v16)) | (~m6 & c6b));
                    float nu6 = fmaf(u6, 0.995f, v6 * 0.00125f);
                    u6 = nu6 + ibits(~m6 & d6b);
                    core6 = fmaf(nv6, fmaf(nv6, 0.01f, 2.25f), fmaf(u6, -0.25f, 35.0f));
                    v6 = nv6;

                    m5p = m5;
                    const int idx = (si & RS_MASK) * 4;
                    ((int*)ring1)[idx + 0] = m5;
                    ring1[idx + 1] = v5;
                    ((int*)ring1)[idx + 2] = m6;
                    ring1[idx + 3] = v6;
                }
            }
            st_rel(&fl[1], b + 1);
        }
        return;
    }

    // ================= warp2: store warp (converts masks -> floats) =================
    if (tid >= 64 && tid < 96) {
        const int lane = tid - 64;
        // rows: z2 z3 z4 z5 z6 v2 v3 v4 v5 v6
        // buf:   0  0  0  1  1  0  0  0  1  1   (mask 0x318)
        // col:   0  1  2  0  2  4  5  6  1  3   ; rows 0-4 are mask rows
        const int* r0i = (const int*)ring0;
        const int* r1i = (const int*)ring1;
        for (int b = 0; b < nbat; ++b) {
            while (ld_acq(&fl[1]) <= b) { }
            const int base = b * BATCH;
            const int n = min(BATCH, T - base);
            if ((T & 3) == 0) {
                const int quads = n >> 2;
                const int units = 10 * quads;
                for (int u = lane; u < units; u += 32) {
                    const int row = u / quads;
                    const int q   = u - row * quads;
                    const int st  = base + q * 4;
                    const int buf = (0x318 >> row) & 1;
                    const int col = (row < 8) ? ((0x65420210u >> (4 * row)) & 15)
                                              : ((0x31u >> (4 * (row - 8))) & 15);
                    int x0, x1, x2, x3;
                    if (buf == 0) {
                        x0 = r0i[((st + 0) & RS_MASK) * 8 + col];
                        x1 = r0i[((st + 1) & RS_MASK) * 8 + col];
                        x2 = r0i[((st + 2) & RS_MASK) * 8 + col];
                        x3 = r0i[((st + 3) & RS_MASK) * 8 + col];
                    } else {
                        x0 = r1i[((st + 0) & RS_MASK) * 4 + col];
                        x1 = r1i[((st + 1) & RS_MASK) * 4 + col];
                        x2 = r1i[((st + 2) & RS_MASK) * 4 + col];
                        x3 = r1i[((st + 3) & RS_MASK) * 4 + col];
                    }
                    if (row < 5) {  // mask -> 0.0/1.0 float bits
                        x0 = ~x0 & 0x3F800000; x1 = ~x1 & 0x3F800000;
                        x2 = ~x2 & 0x3F800000; x3 = ~x3 & 0x3F800000;
                    }
                    *reinterpret_cast<int4*>(&out[row * T + st]) =
                        make_int4(x0, x1, x2, x3);
                }
            } else {
                const int units = 10 * n;
                for (int u = lane; u < units; u += 32) {
                    const int row = u / n;
                    const int i   = u - row * n;
                    const int st  = base + i;
                    const int buf = (0x318 >> row) & 1;
                    const int col = (row < 8) ? ((0x65420210u >> (4 * row)) & 15)
                                              : ((0x31u >> (4 * (row - 8))) & 15);
                    int x = buf ? r1i[(st & RS_MASK) * 4 + col]
                                : r0i[(st & RS_MASK) * 8 + col];
                    if (row < 5) x = ~x & 0x3F800000;
                    ((int*)out)[row * T + st] = x;
                }
            }
            __syncwarp();
            if (lane == 0) st_rel(&fl[2], b + 1);
        }
        return;
    }
}

extern "C" void kernel_launch(void* const* d_in, const int* in_sizes, int n_in,
                              void* d_out, int out_size) {
    const float* in_mat = (const float*)d_in[0];
    const float* w12    = (const float*)d_in[1];
    int n_mat = in_sizes[0];
    int T = out_size / 10;
    izh_net7<<<1, 128>>>(in_mat, n_mat, w12, (float*)d_out, T);
}

// round 7
// speedup vs baseline: 2.3870x; 2.3870x over previous
#include <cuda_runtime.h>

// Izhikevich 6-neuron network, T sequential steps. R2 pipeline (best known: 410us)
// + exact-period detection: constant input => contracting f32 map => bit-periodic
// limit cycle. If full state at a batch boundary bitwise-matches the snapshot at
// step 4096, remaining outputs are copied from the detected cycle.
// warp0: LLBN->EBN->IFN. warp1: TN->MN + detection. warp2: store. all: copy tail.
// Output: [spikes[5][T] | volts[5][T]]

#define BATCH 32
#define RS_MASK 255
#define RING_BATCHES 8
#define SB 128   // snapshot batch -> step 4096

__device__ __forceinline__ float fset_ge30(float a) {
    float r;
    asm("set.ge.f32.f32 %0, %1, %2;" : "=f"(r) : "f"(a), "f"(30.0f));
    return r;
}
__device__ __forceinline__ void st_rel(int* p, int v) {
    asm volatile("st.release.cta.u32 [%0], %1;" :: "l"(p), "r"(v) : "memory");
}
__device__ __forceinline__ int ld_acq(int* p) {
    int v;
    asm volatile("ld.acquire.cta.u32 %0, [%1];" : "=r"(v) : "l"(p) : "memory");
    return v;
}
__device__ __forceinline__ int fb(float x) { return __float_as_int(x); }

__global__ void __launch_bounds__(128, 1)
izh_net8(const float* __restrict__ in_mat, int n_mat,
         const float* __restrict__ w12, float* __restrict__ out, int T) {
    __shared__ __align__(16) float ring0[256 * 8];  // z2,z3,z4,_,v2,v3,v4,_
    __shared__ __align__(16) float ring1[256 * 4];  // z5,v5,z6,v6
    __shared__ float auxst[RING_BATCHES * 8];       // warp0 state at batch starts
    __shared__ float red[4];
    __shared__ int fl[4];   // [0] w0 batches, [1] w1 batches, [2] consumer, [3] det
    __shared__ int detb[1]; // detected batch index

    const int tid = threadIdx.x;
    if (tid == 0) { fl[0] = 0; fl[1] = 0; fl[2] = 0; fl[3] = 0; detb[0] = 0; }

    // ---- reduction: sum(input_mat) ----
    float s = 0.0f;
    for (int i = tid; i < n_mat; i += 128) s += in_mat[i];
    #pragma unroll
    for (int o = 16; o; o >>= 1) s += __shfl_xor_sync(0xffffffffu, s, o);
    if ((tid & 31) == 0) red[tid >> 5] = s;
    __syncthreads();

    const int nbat = (T + BATCH - 1) / BATCH;
    const bool do_det = (T >= (SB + 32) * BATCH / 4) && (T >= 8192);

    // ================= warp0 lane0: LLBN -> EBN -> IFN =================
    if (tid == 0) {
        const float total = red[0] + red[1] + red[2] + red[3];
        const float z_plus = total * w12[0];
        const float C2 = 35.0f + 0.25f * w12[2] * (z_plus * w12[1]);
        const float B2 = 0.25f * w12[3];
        const float A2 = -0.25f * w12[2] * w12[7];
        const float C3 = 35.0f + 0.25f * (z_plus * w12[4]);
        const float A3 = 0.25f * w12[5];
        const float A4 = 0.25f * w12[6];

        float v2 = -60.0f, u2 = 4.5f;
        float v3 = -64.0f, u3 = -16.0f;
        float v4 = -64.0f, u4 = -16.0f;
        float z2p = 0.0f, z4p = 0.0f;

        int si = 0;
        for (int b = 0; b < nbat; ++b) {
            bool stop = false;
            for (;;) {
                if (b - ld_acq(&fl[2]) < RING_BATCHES) break;
                if (ld_acq(&fl[3])) { stop = true; break; }
            }
            if (stop) break;
            // publish state at this batch start (released with fl[0]=b+1)
            {
                float* a = &auxst[(b & (RING_BATCHES - 1)) * 8];
                a[0] = v2; a[1] = u2; a[2] = v3; a[3] = u3;
                a[4] = v4; a[5] = u4; a[6] = z2p; a[7] = z4p;
            }
            const int n = min(BATCH, T - b * BATCH);
            #pragma unroll 4
            for (int i = 0; i < n; ++i, ++si) {
                // LLBN (a=.1,b=-.075,c=-55,d=6)
                float vv2 = v2 * v2;
                float b2  = fmaf(vv2, 0.01f, fmaf(v2, 2.25f, fmaf(u2, -0.25f, C2)));
                float v12 = fmaf(z4p, A2, fmaf(z2p, B2, b2));
                float z2  = fset_ge30(v12);
                float nu2 = fmaf(u2, 0.975f, v2 * -0.001875f);
                v2 = fmaf(z2, -55.0f - v12, v12);
                u2 = fmaf(z2, 6.0f, nu2);
                // EBN (a=.02,b=.25,c=-55,d=.05)
                float vv3 = v3 * v3;
                float b3  = fmaf(vv3, 0.01f, fmaf(v3, 2.25f, fmaf(u3, -0.25f, C3)));
                float v13 = fmaf(z2, A3, b3);
                float z3  = fset_ge30(v13);
                float nu3 = fmaf(u3, 0.995f, v3 * 0.00125f);
                v3 = fmaf(z3, -55.0f - v13, v13);
                u3 = fmaf(z3, 0.05f, nu3);
                // IFN (a=.02,b=.25,c=-65,d=6)
                float vv4 = v4 * v4;
                float b4  = fmaf(vv4, 0.01f, fmaf(v4, 2.25f, fmaf(u4, -0.25f, 35.0f)));
                float v14 = fmaf(z3, A4, b4);
                float z4  = fset_ge30(v14);
                float nu4 = fmaf(u4, 0.995f, v4 * 0.00125f);
                v4 = fmaf(z4, -65.0f - v14, v14);
                u4 = fmaf(z4, 6.0f, nu4);

                z2p = z2; z4p = z4;
                float4* r = (float4*)&ring0[(si & RS_MASK) * 8];
                r[0] = make_float4(z2, z3, z4, 0.0f);
                r[1] = make_float4(v2, v3, v4, 0.0f);
            }
            st_rel(&fl[0], b + 1);
        }
    }

    // ================= warp1 lane0: TN -> MN + period detection =================
    if (tid == 32) {
        const float A5 = 0.25f * w12[9] * w12[8];
        const float B5 = 0.25f * w12[10];
        const float A6 = 0.25f * w12[11];
        float v5 = -70.0f, u5 = -14.0f;
        float v6 = -64.0f, u6 = -16.0f;
        float z5p = 0.0f;
        float snap[13];

        int si = 0;
        for (int b = 0; b < nbat; ++b) {
            while (ld_acq(&fl[0]) <= b) { }
            if (do_det && b >= SB) {
                const float* a = &auxst[(b & (RING_BATCHES - 1)) * 8];
                if (b == SB) {
                    #pragma unroll
                    for (int k = 0; k < 8; ++k) snap[k] = a[k];
                    snap[8] = v5; snap[9] = u5; snap[10] = v6; snap[11] = u6;
                    snap[12] = z5p;
                } else {
                    bool eq = (fb(a[0]) == fb(snap[0])) & (fb(a[1]) == fb(snap[1])) &
                              (fb(a[2]) == fb(snap[2])) & (fb(a[3]) == fb(snap[3])) &
                              (fb(a[4]) == fb(snap[4])) & (fb(a[5]) == fb(snap[5])) &
                              (fb(a[6]) == fb(snap[6])) & (fb(a[7]) == fb(snap[7])) &
                              (fb(v5) == fb(snap[8])) & (fb(u5) == fb(snap[9])) &
                              (fb(v6) == fb(snap[10])) & (fb(u6) == fb(snap[11])) &
                              (fb(z5p) == fb(snap[12]));
                    if (eq) {
                        detb[0] = b;
                        st_rel(&fl[3], 1);
                        break;   // outputs from b*32 on are periodic copies
                    }
                }
            }
            const int n = min(BATCH, T - b * BATCH);
            #pragma unroll 4
            for (int i = 0; i < n; ++i, ++si) {
                float z3 = ring0[(si & RS_MASK) * 8 + 1];
                // TN (a=.02,b=.2,c=-65,d=6)
                float vv5 = v5 * v5;
                float b5  = fmaf(vv5, 0.01f, fmaf(v5, 2.25f, fmaf(u5, -0.25f, 35.0f)));
                float v15 = fmaf(z5p, B5, fmaf(z3, A5, b5));
                float z5  = fset_ge30(v15);
                float nu5 = fmaf(u5, 0.995f, v5 * 0.001f);
                v5 = fmaf(z5, -65.0f - v15, v15);
                u5 = fmaf(z5, 6.0f, nu5);
                // MN (a=.02,b=.25,c=-65,d=6)
                float vv6 = v6 * v6;
                float b6  = fmaf(vv6, 0.01f, fmaf(v6, 2.25f, fmaf(u6, -0.25f, 35.0f)));
                float v16 = fmaf(z5, A6, b6);
                float z6  = fset_ge30(v16);
                float nu6 = fmaf(u6, 0.995f, v6 * 0.00125f);
                v6 = fmaf(z6, -65.0f - v16, v16);
                u6 = fmaf(z6, 6.0f, nu6);

                z5p = z5;
                ((float4*)&ring1[(si & RS_MASK) * 4])[0] = make_float4(z5, v5, z6, v6);
            }
            st_rel(&fl[1], b + 1);
        }
    }

    // ================= warp2: store warp =================
    if (tid >= 64 && tid < 96) {
        const int lane = tid - 64;
        // rows: z2 z3 z4 z5 z6 v2 v3 v4 v5 v6 ; buf mask 0x318 ; cols 0,1,2,0,2,4,5,6,1,3
        for (int b = 0; b < nbat; ++b) {
            bool stop = false;
            for (;;) {
                if (ld_acq(&fl[1]) > b) break;
                if (ld_acq(&fl[3])) {
                    if (ld_acq(&fl[1]) <= b) stop = true;
                    if (stop) break;
                }
            }
            if (stop) break;
            const int base = b * BATCH;
            const int n = min(BATCH, T - base);
            if ((T & 3) == 0) {
                const int quads = n >> 2;
                const int units = 10 * quads;
                for (int u = lane; u < units; u += 32) {
                    const int row = u / quads;
                    const int q   = u - row * quads;
                    const int st  = base + q * 4;
                    const int buf = (0x318 >> row) & 1;
                    const int col = (row < 8) ? ((0x65420210u >> (4 * row)) & 15)
                                              : ((0x31u >> (4 * (row - 8))) & 15);
                    float x0, x1, x2, x3;
                    if (buf == 0) {
                        x0 = ring0[((st + 0) & RS_MASK) * 8 + col];
                        x1 = ring0[((st + 1) & RS_MASK) * 8 + col];
                        x2 = ring0[((st + 2) & RS_MASK) * 8 + col];
                        x3 = ring0[((st + 3) & RS_MASK) * 8 + col];
                    } else {
                        x0 = ring1[((st + 0) & RS_MASK) * 4 + col];
                        x1 = ring1[((st + 1) & RS_MASK) * 4 + col];
                        x2 = ring1[((st + 2) & RS_MASK) * 4 + col];
                        x3 = ring1[((st + 3) & RS_MASK) * 4 + col];
                    }
                    *(float4*)&out[row * T + st] = make_float4(x0, x1, x2, x3);
                }
            } else {
                const int units = 10 * n;
                for (int u = lane; u < units; u += 32) {
                    const int row = u / n;
                    const int i   = u - row * n;
                    const int st  = base + i;
                    const int buf = (0x318 >> row) & 1;
                    const int col = (row < 8) ? ((0x65420210u >> (4 * row)) & 15)
                                              : ((0x31u >> (4 * (row - 8))) & 15);
                    float x = buf ? ring1[(st & RS_MASK) * 4 + col]
                                  : ring0[(st & RS_MASK) * 8 + col];
                    out[row * T + st] = x;
                }
            }
            __syncwarp();
            if (lane == 0) st_rel(&fl[2], b + 1);
        }
    }

    // ================= periodic tail copy (all 128 threads) =================
    __syncthreads();
    if (fl[3]) {
        const int b1   = detb[0];
        const int tcut = b1 * BATCH;
        const int t0   = SB * BATCH;
        const int P    = tcut - t0;
        for (int r = 0; r < 10; ++r) {
            float* row = out + r * T;
            for (int t = tcut + tid; t < T; t += 128) {
                int src = t0 + (t - t0) % P;
                row[t] = row[src];
            }
        }
    }
}

extern "C" void kernel_launch(void* const* d_in, const int* in_sizes, int n_in,
                              void* d_out, int out_size) {
    const float* in_mat = (const float*)d_in[0];
    const float* w12    = (const float*)d_in[1];
    int n_mat = in_sizes[0];
    int T = out_size / 10;
    izh_net8<<<1, 128>>>(in_mat, n_mat, w12, (float*)d_out, T);
}

// round 8
// speedup vs baseline: 4.3034x; 1.8028x over previous
#include <cuda_runtime.h>

// Izhikevich 6-neuron network, T sequential steps. R2 pipeline + snapshot-ladder
// exact period detection + grid-parallel tail copy (2nd kernel).
// warp0: LLBN->EBN->IFN. warp1: TN->MN + ladder detection. warp2: store.
// Output: [spikes[5][T] | volts[5][T]]

#define BATCH 32
#define RS_MASK 255
#define RING_BATCHES 8
#define AUX_MASK 15          // 16-deep aux state ring (> RING_BATCHES)
#define NRUNG 4

__device__ int g_det[3];     // [0]=flag, [1]=tcut (step), [2]=t0 (step)

__device__ __forceinline__ float fset_ge30(float a) {
    float r;
    asm("set.ge.f32.f32 %0, %1, %2;" : "=f"(r) : "f"(a), "f"(30.0f));
    return r;
}
__device__ __forceinline__ void st_rel(int* p, int v) {
    asm volatile("st.release.cta.u32 [%0], %1;" :: "l"(p), "r"(v) : "memory");
}
__device__ __forceinline__ int ld_acq(int* p) {
    int v;
    asm volatile("ld.acquire.cta.u32 %0, [%1];" : "=r"(v) : "l"(p) : "memory");
    return v;
}
__device__ __forceinline__ int fb(float x) { return __float_as_int(x); }

__global__ void __launch_bounds__(128, 1)
izh_sim(const float* __restrict__ in_mat, int n_mat,
        const float* __restrict__ w12, float* __restrict__ out, int T) {
    __shared__ __align__(16) float ring0[256 * 8];  // z2,z3,z4,_,v2,v3,v4,_
    __shared__ __align__(16) float ring1[256 * 4];  // z5,v5,z6,v6
    __shared__ float auxst[16 * 8];                 // warp0 state @ batch starts
    __shared__ float snaps[NRUNG][13];
    __shared__ float red[4];
    __shared__ int fl[4];   // [0] w0 batches, [1] w1 batches, [2] consumer, [3] det

    const int tid = threadIdx.x;
    if (tid == 0) { fl[0] = 0; fl[1] = 0; fl[2] = 0; fl[3] = 0; }

    // ---- reduction: sum(input_mat) ----
    float s = 0.0f;
    for (int i = tid; i < n_mat; i += 128) s += in_mat[i];
    #pragma unroll
    for (int o = 16; o; o >>= 1) s += __shfl_xor_sync(0xffffffffu, s, o);
    if ((tid & 31) == 0) red[tid >> 5] = s;
    __syncthreads();

    const int nbat = (T + BATCH - 1) / BATCH;

    // ================= warp0 lane0: LLBN -> EBN -> IFN =================
    if (tid == 0) {
        const float total = red[0] + red[1] + red[2] + red[3];
        const float z_plus = total * w12[0];
        const float C2 = 35.0f + 0.25f * w12[2] * (z_plus * w12[1]);
        const float B2 = 0.25f * w12[3];
        const float A2 = -0.25f * w12[2] * w12[7];
        const float C3 = 35.0f + 0.25f * (z_plus * w12[4]);
        const float A3 = 0.25f * w12[5];
        const float A4 = 0.25f * w12[6];

        float v2 = -60.0f, u2 = 4.5f;
        float v3 = -64.0f, u3 = -16.0f;
        float v4 = -64.0f, u4 = -16.0f;
        float z2p = 0.0f, z4p = 0.0f;

        int si = 0;
        for (int b = 0; b < nbat; ++b) {
            if (ld_acq(&fl[3])) break;
            bool stop = false;
            for (;;) {
                if (b - ld_acq(&fl[2]) < RING_BATCHES) break;
                if (ld_acq(&fl[3])) { stop = true; break; }
            }
            if (stop) break;
            {   // publish state at this batch start (released by fl[0]=b+1)
                float* a = &auxst[(b & AUX_MASK) * 8];
                a[0] = v2; a[1] = u2; a[2] = v3; a[3] = u3;
                a[4] = v4; a[5] = u4; a[6] = z2p; a[7] = z4p;
            }
            const int n = min(BATCH, T - b * BATCH);
            #pragma unroll 4
            for (int i = 0; i < n; ++i, ++si) {
                // LLBN (a=.1,b=-.075,c=-55,d=6)
                float vv2 = v2 * v2;
                float b2  = fmaf(vv2, 0.01f, fmaf(v2, 2.25f, fmaf(u2, -0.25f, C2)));
                float v12 = fmaf(z4p, A2, fmaf(z2p, B2, b2));
                float z2  = fset_ge30(v12);
                float nu2 = fmaf(u2, 0.975f, v2 * -0.001875f);
                v2 = fmaf(z2, -55.0f - v12, v12);
                u2 = fmaf(z2, 6.0f, nu2);
                // EBN (a=.02,b=.25,c=-55,d=.05)
                float vv3 = v3 * v3;
                float b3  = fmaf(vv3, 0.01f, fmaf(v3, 2.25f, fmaf(u3, -0.25f, C3)));
                float v13 = fmaf(z2, A3, b3);
                float z3  = fset_ge30(v13);
                float nu3 = fmaf(u3, 0.995f, v3 * 0.00125f);
                v3 = fmaf(z3, -55.0f - v13, v13);
                u3 = fmaf(z3, 0.05f, nu3);
                // IFN (a=.02,b=.25,c=-65,d=6)
                float vv4 = v4 * v4;
                float b4  = fmaf(vv4, 0.01f, fmaf(v4, 2.25f, fmaf(u4, -0.25f, 35.0f)));
                float v14 = fmaf(z3, A4, b4);
                float z4  = fset_ge30(v14);
                float nu4 = fmaf(u4, 0.995f, v4 * 0.00125f);
                v4 = fmaf(z4, -65.0f - v14, v14);
                u4 = fmaf(z4, 6.0f, nu4);

                z2p = z2; z4p = z4;
                float4* r = (float4*)&ring0[(si & RS_MASK) * 8];
                r[0] = make_float4(z2, z3, z4, 0.0f);
                r[1] = make_float4(v2, v3, v4, 0.0f);
            }
            st_rel(&fl[0], b + 1);
        }
    }

    // ================= warp1 lane0: TN -> MN + ladder detection =================
    if (tid == 32) {
        const int RUNG[NRUNG] = {40, 72, 104, 128};   // steps 1280,2304,3328,4096
        bool armed[NRUNG] = {false, false, false, false};
        const float A5 = 0.25f * w12[9] * w12[8];
        const float B5 = 0.25f * w12[10];
        const float A6 = 0.25f * w12[11];
        float v5 = -70.0f, u5 = -14.0f;
        float v6 = -64.0f, u6 = -16.0f;
        float z5p = 0.0f;
        bool fired = false;
        int t0b = 0, tcb = 0;

        int si = 0;
        for (int b = 0; b < nbat; ++b) {
            while (ld_acq(&fl[0]) <= b) { }
            if (b >= RUNG[0]) {
                const float* a = &auxst[(b & AUX_MASK) * 8];
                float cur[13];
                cur[0] = a[0]; cur[1] = a[1]; cur[2] = a[2]; cur[3] = a[3];
                cur[4] = a[4]; cur[5] = a[5]; cur[6] = a[6]; cur[7] = a[7];
                cur[8] = v5; cur[9] = u5; cur[10] = v6; cur[11] = u6; cur[12] = z5p;
                #pragma unroll
                for (int r = 0; r < NRUNG; ++r) {
                    if (armed[r]) {
                        bool eq = true;
                        #pragma unroll
                        for (int k = 0; k < 13; ++k)
                            eq &= (fb(cur[k]) == fb(snaps[r][k]));
                        if (eq) { fired = true; t0b = RUNG[r]; }
                    }
                }
                if (fired) {
                    tcb = b;
                    st_rel(&fl[3], 1);
                    break;
                }
                #pragma unroll
                for (int r = 0; r < NRUNG; ++r) {
                    if (b == RUNG[r]) {
                        #pragma unroll
                        for (int k = 0; k < 13; ++k) snaps[r][k] = cur[k];
                        armed[r] = true;
                    }
                }
            }
            const int n = min(BATCH, T - b * BATCH);
            #pragma unroll 4
            for (int i = 0; i < n; ++i, ++si) {
                float z3 = ring0[(si & RS_MASK) * 8 + 1];
                // TN (a=.02,b=.2,c=-65,d=6)
                float vv5 = v5 * v5;
                float b5  = fmaf(vv5, 0.01f, fmaf(v5, 2.25f, fmaf(u5, -0.25f, 35.0f)));
                float v15 = fmaf(z5p, B5, fmaf(z3, A5, b5));
                float z5  = fset_ge30(v15);
                float nu5 = fmaf(u5, 0.995f, v5 * 0.001f);
                v5 = fmaf(z5, -65.0f - v15, v15);
                u5 = fmaf(z5, 6.0f, nu5);
                // MN (a=.02,b=.25,c=-65,d=6)
                float vv6 = v6 * v6;
                float b6  = fmaf(vv6, 0.01f, fmaf(v6, 2.25f, fmaf(u6, -0.25f, 35.0f)));
                float v16 = fmaf(z5, A6, b6);
                float z6  = fset_ge30(v16);
                float nu6 = fmaf(u6, 0.995f, v6 * 0.00125f);
                v6 = fmaf(z6, -65.0f - v16, v16);
                u6 = fmaf(z6, 6.0f, nu6);

                z5p = z5;
                ((float4*)&ring1[(si & RS_MASK) * 4])[0] = make_float4(z5, v5, z6, v6);
            }
            st_rel(&fl[1], b + 1);
        }
        // publish detection result for the copy kernel (every launch rewrites it)
        g_det[0] = fired ? 1 : 0;
        g_det[1] = tcb * BATCH;
        g_det[2] = t0b * BATCH;
    }

    // ================= warp2: store warp =================
    if (tid >= 64 && tid < 96) {
        const int lane = tid - 64;
        // rows: z2 z3 z4 z5 z6 v2 v3 v4 v5 v6 ; buf mask 0x318 ; cols 0,1,2,0,2,4,5,6,1,3
        for (int b = 0; b < nbat; ++b) {
            bool stop = false;
            for (;;) {
                if (ld_acq(&fl[1]) > b) break;
                if (ld_acq(&fl[3]) && ld_acq(&fl[1]) <= b) { stop = true; break; }
            }
            if (stop) break;
            const int base = b * BATCH;
            const int n = min(BATCH, T - base);
            if ((T & 3) == 0) {
                const int quads = n >> 2;
                const int units = 10 * quads;
                for (int u = lane; u < units; u += 32) {
                    const int row = u / quads;
                    const int q   = u - row * quads;
                    const int st  = base + q * 4;
                    const int buf = (0x318 >> row) & 1;
                    const int col = (row < 8) ? ((0x65420210u >> (4 * row)) & 15)
                                              : ((0x31u >> (4 * (row - 8))) & 15);
                    float x0, x1, x2, x3;
                    if (buf == 0) {
                        x0 = ring0[((st + 0) & RS_MASK) * 8 + col];
                        x1 = ring0[((st + 1) & RS_MASK) * 8 + col];
                        x2 = ring0[((st + 2) & RS_MASK) * 8 + col];
                        x3 = ring0[((st + 3) & RS_MASK) * 8 + col];
                    } else {
                        x0 = ring1[((st + 0) & RS_MASK) * 4 + col];
                        x1 = ring1[((st + 1) & RS_MASK) * 4 + col];
                        x2 = ring1[((st + 2) & RS_MASK) * 4 + col];
                        x3 = ring1[((st + 3) & RS_MASK) * 4 + col];
                    }
                    *(float4*)&out[row * T + st] = make_float4(x0, x1, x2, x3);
                }
            } else {
                const int units = 10 * n;
                for (int u = lane; u < units; u += 32) {
                    const int row = u / n;
                    const int i   = u - row * n;
                    const int st  = base + i;
                    const int buf = (0x318 >> row) & 1;
                    const int col = (row < 8) ? ((0x65420210u >> (4 * row)) & 15)
                                              : ((0x31u >> (4 * (row - 8))) & 15);
                    float x = buf ? ring1[(st & RS_MASK) * 4 + col]
                                  : ring0[(st & RS_MASK) * 8 + col];
                    out[row * T + st] = x;
                }
            }
            __syncwarp();
            if (lane == 0) st_rel(&fl[2], b + 1);
        }
    }
}

// Grid-parallel periodic tail fill: out[r][t] = out[r][t0 + (t-t0) mod P] for t >= tcut.
__global__ void izh_tail_copy(float* __restrict__ out, int T) {
    if (!g_det[0]) return;
    const int tcut = g_det[1];
    const int t0   = g_det[2];
    const int P    = tcut - t0;
    const int tail = T - tcut;
    if (tail <= 0 || P <= 0) return;
    const int total = 10 * tail;
    for (int idx = blockIdx.x * blockDim.x + threadIdx.x; idx < total;
         idx += gridDim.x * blockDim.x) {
        const int row = idx / tail;
        const int t   = tcut + (idx - row * tail);
        const int src = t0 + (t - t0) % P;
        out[row * T + t] = out[row * T + src];
    }
}

extern "C" void kernel_launch(void* const* d_in, const int* in_sizes, int n_in,
                              void* d_out, int out_size) {
    const float* in_mat = (const float*)d_in[0];
    const float* w12    = (const float*)d_in[1];
    int n_mat = in_sizes[0];
    int T = out_size / 10;
    izh_sim<<<1, 128>>>(in_mat, n_mat, w12, (float*)d_out, T);
    izh_tail_copy<<<256, 256>>>((float*)d_out, T);
}